// round 1
// baseline (speedup 1.0000x reference)
#include <cuda_runtime.h>
#include <cuda_bf16.h>

#define NN   100000
#define NE   1600000
#define NG   4096
#define HID  128
#define FIN  11
#define FOUT 19
#define NT   (NE + NN)   // edges + self loops

// ---- scratch (static device globals; no allocation) ----
__device__ int   g_cnt[NN];          // degree incl. self-loop (int)
__device__ float g_dinv[NN];         // deg^-1/2
__device__ int   g_off[NN + 1];      // CSR row offsets (by dst)
__device__ int   g_cur[NN];          // fill cursors
__device__ int   g_col[NT];          // CSR col = src node
__device__ float g_w[NT];            // edge weight dinv[s]*dinv[d]
__device__ float g_agg1[NN * FIN];   // A_norm @ x
__device__ float g_h1[NN * HID];     // relu(agg1 @ W1 + b1)
__device__ float g_pool[NG * HID];   // segment sums of A_norm @ h1
__device__ int   g_gcnt[NG];         // nodes per graph
__device__ float g_wf[HID * FOUT];   // W2 @ Wlin
__device__ float g_bf[FOUT];         // b2 @ Wlin + blin

// ---- kernels ----
__global__ void k_init() {
    int i = blockIdx.x * blockDim.x + threadIdx.x;
    if (i < NN)        g_cnt[i] = 1;       // self-loop
    if (i < NG * HID)  g_pool[i] = 0.0f;
    if (i < NG)        g_gcnt[i] = 0;
}

__global__ void k_deg(const int* __restrict__ dst) {
    int e = blockIdx.x * blockDim.x + threadIdx.x;
    if (e < NE) atomicAdd(&g_cnt[dst[e]], 1);
}

__global__ void k_dinv(const int* __restrict__ batch) {
    int i = blockIdx.x * blockDim.x + threadIdx.x;
    if (i < NN) {
        g_dinv[i] = rsqrtf((float)g_cnt[i]);   // cnt >= 1 always
        atomicAdd(&g_gcnt[batch[i]], 1);
    }
}

// single-block exclusive scan of g_cnt -> g_off, g_cur
__global__ void k_scan() {
    __shared__ int ssum[1024];
    const int T = 1024;
    const int CH = (NN + T - 1) / T;   // 98
    int t = threadIdx.x;
    int start = t * CH;
    int end = start + CH; if (end > NN) end = NN; if (start > NN) start = NN;
    int s = 0;
    for (int i = start; i < end; i++) s += g_cnt[i];
    ssum[t] = s;
    __syncthreads();
    for (int off = 1; off < T; off <<= 1) {
        int v = 0;
        if (t >= off) v = ssum[t - off];
        __syncthreads();
        if (t >= off) ssum[t] += v;
        __syncthreads();
    }
    int run = (t == 0) ? 0 : ssum[t - 1];
    for (int i = start; i < end; i++) {
        int c = g_cnt[i];
        g_off[i] = run;
        g_cur[i] = run;
        run += c;
    }
    if (t == T - 1) g_off[NN] = ssum[T - 1];
}

__global__ void k_fill(const int* __restrict__ src, const int* __restrict__ dst) {
    int t = blockIdx.x * blockDim.x + threadIdx.x;
    if (t >= NT) return;
    int s, d;
    if (t < NE) { s = src[t]; d = dst[t]; }
    else        { s = d = t - NE; }          // self-loop
    int p = atomicAdd(&g_cur[d], 1);
    g_col[p] = s;
    g_w[p] = g_dinv[s] * g_dinv[d];
}

// agg1[i] = sum_j w * x[col[j]]  (11 features, warp per node, lanes 0..10)
__global__ void k_agg1(const float* __restrict__ x) {
    int warp = (blockIdx.x * blockDim.x + threadIdx.x) >> 5;
    int lane = threadIdx.x & 31;
    if (warp >= NN) return;
    int beg = g_off[warp], end = g_off[warp + 1];
    float acc = 0.0f;
    for (int j = beg; j < end; j++) {
        int c = g_col[j];          // broadcast load
        float wt = g_w[j];
        if (lane < FIN) acc += wt * __ldg(&x[c * FIN + lane]);
    }
    if (lane < FIN) g_agg1[warp * FIN + lane] = acc;
}

// h1 = relu(agg1 @ W1 + b1); 128 threads, 16 nodes per block
#define GB_NODES 16
__global__ void k_gemm1(const float* __restrict__ W1, const float* __restrict__ b1) {
    __shared__ float sW[FIN * HID];
    __shared__ float sb[HID];
    __shared__ float srow[GB_NODES * FIN];
    int t = threadIdx.x;                    // 0..127 = output feature
    for (int k = t; k < FIN * HID; k += 128) sW[k] = W1[k];
    sb[t] = b1[t];
    int nb = blockIdx.x * GB_NODES;
    for (int k = t; k < GB_NODES * FIN; k += 128) {
        int node = nb + k / FIN;
        srow[k] = (node < NN) ? g_agg1[node * FIN + (k % FIN)] : 0.0f;
    }
    __syncthreads();
    float wc[FIN];
#pragma unroll
    for (int k = 0; k < FIN; k++) wc[k] = sW[k * HID + t];
#pragma unroll
    for (int n = 0; n < GB_NODES; n++) {
        int node = nb + n;
        if (node >= NN) break;
        float acc = sb[t];
#pragma unroll
        for (int k = 0; k < FIN; k++) acc += srow[n * FIN + k] * wc[k];
        g_h1[(size_t)node * HID + t] = fmaxf(acc, 0.0f);
    }
}

// fuse W2@Wlin and b2@Wlin+blin
__global__ void k_fuse(const float* __restrict__ W2, const float* __restrict__ Wlin,
                       const float* __restrict__ b2, const float* __restrict__ blin) {
    int t = blockIdx.x * blockDim.x + threadIdx.x;
    if (t < HID * FOUT) {
        int f = t / FOUT, o = t % FOUT;
        float acc = 0.0f;
        for (int m = 0; m < HID; m++) acc += W2[f * HID + m] * Wlin[m * FOUT + o];
        g_wf[t] = acc;
    }
    if (t < FOUT) {
        float acc = blin[t];
        for (int m = 0; m < HID; m++) acc += b2[m] * Wlin[m * FOUT + t];
        g_bf[t] = acc;
    }
}

// agg2 row (128 feats) via CSR gather, reduce straight into pooled sums
__global__ void k_agg2(const int* __restrict__ batch) {
    int warp = (blockIdx.x * blockDim.x + threadIdx.x) >> 5;
    int lane = threadIdx.x & 31;
    if (warp >= NN) return;
    int beg = g_off[warp], end = g_off[warp + 1];
    const float4* h4 = (const float4*)g_h1;
    float4 acc = make_float4(0.f, 0.f, 0.f, 0.f);
    int j = beg;
    // 4-wide unroll for MLP on the random h1 loads
    for (; j + 3 < end; j += 4) {
        int c0 = g_col[j],   c1 = g_col[j+1], c2 = g_col[j+2], c3 = g_col[j+3];
        float w0 = g_w[j],   w1 = g_w[j+1],   w2 = g_w[j+2],   w3 = g_w[j+3];
        float4 v0 = h4[c0 * 32 + lane];
        float4 v1 = h4[c1 * 32 + lane];
        float4 v2 = h4[c2 * 32 + lane];
        float4 v3 = h4[c3 * 32 + lane];
        acc.x += w0*v0.x + w1*v1.x + w2*v2.x + w3*v3.x;
        acc.y += w0*v0.y + w1*v1.y + w2*v2.y + w3*v3.y;
        acc.z += w0*v0.z + w1*v1.z + w2*v2.z + w3*v3.z;
        acc.w += w0*v0.w + w1*v1.w + w2*v2.w + w3*v3.w;
    }
    for (; j < end; j++) {
        int c = g_col[j]; float wt = g_w[j];
        float4 v = h4[c * 32 + lane];
        acc.x += wt * v.x; acc.y += wt * v.y; acc.z += wt * v.z; acc.w += wt * v.w;
    }
    float* p = &g_pool[batch[warp] * HID + lane * 4];
    atomicAdd(p + 0, acc.x);
    atomicAdd(p + 1, acc.y);
    atomicAdd(p + 2, acc.z);
    atomicAdd(p + 3, acc.w);
}

// out[g] = (pool[g]/cnt) @ Wf + bf   (warp per graph, lanes 0..18)
__global__ void k_out(const float* __restrict__ blin, float* __restrict__ out) {
    int warp = (blockIdx.x * blockDim.x + threadIdx.x) >> 5;
    int lane = threadIdx.x & 31;
    if (warp >= NG || lane >= FOUT) return;
    int cnt = g_gcnt[warp];
    float inv = (cnt > 0) ? (1.0f / (float)cnt) : 0.0f;
    float acc = (cnt > 0) ? g_bf[lane] : blin[lane];
    for (int f = 0; f < HID; f++)
        acc += (g_pool[warp * HID + f] * inv) * g_wf[f * FOUT + lane];
    out[warp * FOUT + lane] = acc;
}

extern "C" void kernel_launch(void* const* d_in, const int* in_sizes, int n_in,
                              void* d_out, int out_size) {
    const float* x    = (const float*)d_in[0];
    const int*   esrc = (const int*)d_in[1];
    const int*   edst = (const int*)d_in[2];
    const int*   batch= (const int*)d_in[3];
    const float* W1   = (const float*)d_in[4];
    const float* b1   = (const float*)d_in[5];
    const float* W2   = (const float*)d_in[6];
    const float* b2   = (const float*)d_in[7];
    const float* Wlin = (const float*)d_in[8];
    const float* blin = (const float*)d_in[9];
    float* out = (float*)d_out;

    k_init <<<(NG * HID + 255) / 256, 256>>>();
    k_deg  <<<(NE + 255) / 256, 256>>>(edst);
    k_dinv <<<(NN + 255) / 256, 256>>>(batch);
    k_scan <<<1, 1024>>>();
    k_fill <<<(NT + 255) / 256, 256>>>(esrc, edst);
    k_agg1 <<<(NN * 32 + 255) / 256, 256>>>(x);
    k_gemm1<<<(NN + GB_NODES - 1) / GB_NODES, 128>>>(W1, b1);
    k_fuse <<<10, 256>>>(W2, Wlin, b2, blin);
    k_agg2 <<<(NN * 32 + 255) / 256, 256>>>(batch);
    k_out  <<<(NG * 32 + 255) / 256, 256>>>(blin, out);
}

// round 2
// speedup vs baseline: 1.6967x; 1.6967x over previous
#include <cuda_runtime.h>
#include <cuda_bf16.h>

#define NN   100000
#define NE   1600000
#define NG   4096
#define HID  128
#define FIN  11
#define FOUT 19
#define NT   (NE + NN)   // edges + self loops
#define SCAN_B 1024
#define NB   ((NN + SCAN_B - 1) / SCAN_B)   // 98

// ---- scratch (static device globals; no allocation) ----
__device__ int   g_cnt[NN];          // degree incl. self-loop (int)
__device__ float g_dinv[NN];         // deg^-1/2
__device__ int   g_off[NN + 1];      // CSR row offsets (by dst)
__device__ int   g_cur[NN];          // fill cursors
__device__ int   g_col[NT];          // CSR col = src node
__device__ float g_w[NT];            // edge weight dinv[s]*dinv[d]
__device__ int   g_bsum[NB];         // per-block sums for scan
__device__ int   g_bpre[NB];         // scanned block prefixes
__device__ float g_agg1[NN * FIN];   // A_norm @ x
__device__ float g_h1[NN * HID];     // relu(agg1 @ W1 + b1)
__device__ float g_pool[NG * HID];   // segment sums of A_norm @ h1
__device__ int   g_gcnt[NG];         // nodes per graph
__device__ float g_wf[HID * FOUT];   // W2 @ Wlin
__device__ float g_bf[FOUT];         // b2 @ Wlin + blin

// ---- kernels ----
__global__ void k_init() {
    int i = blockIdx.x * blockDim.x + threadIdx.x;
    if (i < NN)        g_cnt[i] = 1;       // self-loop
    if (i < NG * HID)  g_pool[i] = 0.0f;
    if (i < NG)        g_gcnt[i] = 0;
}

__global__ void k_deg(const int* __restrict__ dst) {
    int e = blockIdx.x * blockDim.x + threadIdx.x;
    if (e < NE) atomicAdd(&g_cnt[dst[e]], 1);
}

__global__ void k_dinv(const int* __restrict__ batch) {
    int i = blockIdx.x * blockDim.x + threadIdx.x;
    if (i < NN) {
        g_dinv[i] = rsqrtf((float)g_cnt[i]);   // cnt >= 1 always
        atomicAdd(&g_gcnt[batch[i]], 1);
    }
}

// ---- 3-phase parallel scan of g_cnt -> g_off (exclusive), g_cur ----
// Phase A: per-block inclusive scan; write exclusive (sans block prefix) + block sum
__global__ void k_scanA() {
    __shared__ int s[SCAN_B];
    int t = threadIdx.x;
    int i = blockIdx.x * SCAN_B + t;
    int c = (i < NN) ? g_cnt[i] : 0;
    s[t] = c;
    __syncthreads();
#pragma unroll
    for (int off = 1; off < SCAN_B; off <<= 1) {
        int v = (t >= off) ? s[t - off] : 0;
        __syncthreads();
        if (t >= off) s[t] += v;
        __syncthreads();
    }
    if (i < NN) g_off[i] = s[t] - c;       // exclusive, local
    if (t == SCAN_B - 1) g_bsum[blockIdx.x] = s[t];
}

// Phase B: scan the NB block sums (single small block)
__global__ void k_scanB() {
    __shared__ int s[128];
    int t = threadIdx.x;
    int v = (t < NB) ? g_bsum[t] : 0;
    s[t] = v;
    __syncthreads();
#pragma unroll
    for (int off = 1; off < 128; off <<= 1) {
        int u = (t >= off) ? s[t - off] : 0;
        __syncthreads();
        if (t >= off) s[t] += u;
        __syncthreads();
    }
    if (t < NB) g_bpre[t] = s[t] - v;      // exclusive prefix
    if (t == 127) g_off[NN] = s[127];      // total = NT
}

// Phase C: add block prefix, set cursors
__global__ void k_scanC() {
    int i = blockIdx.x * blockDim.x + threadIdx.x;
    if (i < NN) {
        int o = g_off[i] + g_bpre[i / SCAN_B];
        g_off[i] = o;
        g_cur[i] = o;
    }
}

__global__ void k_fill(const int* __restrict__ src, const int* __restrict__ dst) {
    int t = blockIdx.x * blockDim.x + threadIdx.x;
    if (t >= NT) return;
    int s, d;
    if (t < NE) { s = src[t]; d = dst[t]; }
    else        { s = d = t - NE; }          // self-loop
    int p = atomicAdd(&g_cur[d], 1);
    g_col[p] = s;
    g_w[p] = g_dinv[s] * g_dinv[d];
}

// agg1[i] = sum_j w * x[col[j]]  (11 features, warp per node, lanes 0..10)
__global__ void k_agg1(const float* __restrict__ x) {
    int warp = (blockIdx.x * blockDim.x + threadIdx.x) >> 5;
    int lane = threadIdx.x & 31;
    if (warp >= NN) return;
    int beg = g_off[warp], end = g_off[warp + 1];
    float acc = 0.0f;
    for (int j = beg; j < end; j++) {
        int c = g_col[j];          // broadcast load
        float wt = g_w[j];
        if (lane < FIN) acc += wt * __ldg(&x[c * FIN + lane]);
    }
    if (lane < FIN) g_agg1[warp * FIN + lane] = acc;
}

// h1 = relu(agg1 @ W1 + b1); 128 threads, 16 nodes per block
#define GB_NODES 16
__global__ void k_gemm1(const float* __restrict__ W1, const float* __restrict__ b1) {
    __shared__ float sW[FIN * HID];
    __shared__ float sb[HID];
    __shared__ float srow[GB_NODES * FIN];
    int t = threadIdx.x;                    // 0..127 = output feature
    for (int k = t; k < FIN * HID; k += 128) sW[k] = W1[k];
    sb[t] = b1[t];
    int nb = blockIdx.x * GB_NODES;
    for (int k = t; k < GB_NODES * FIN; k += 128) {
        int node = nb + k / FIN;
        srow[k] = (node < NN) ? g_agg1[node * FIN + (k % FIN)] : 0.0f;
    }
    __syncthreads();
    float wc[FIN];
#pragma unroll
    for (int k = 0; k < FIN; k++) wc[k] = sW[k * HID + t];
#pragma unroll
    for (int n = 0; n < GB_NODES; n++) {
        int node = nb + n;
        if (node >= NN) break;
        float acc = sb[t];
#pragma unroll
        for (int k = 0; k < FIN; k++) acc += srow[n * FIN + k] * wc[k];
        g_h1[(size_t)node * HID + t] = fmaxf(acc, 0.0f);
    }
}

// fuse W2@Wlin and b2@Wlin+blin
__global__ void k_fuse(const float* __restrict__ W2, const float* __restrict__ Wlin,
                       const float* __restrict__ b2, const float* __restrict__ blin) {
    int t = blockIdx.x * blockDim.x + threadIdx.x;
    if (t < HID * FOUT) {
        int f = t / FOUT, o = t % FOUT;
        float acc = 0.0f;
        for (int m = 0; m < HID; m++) acc += W2[f * HID + m] * Wlin[m * FOUT + o];
        g_wf[t] = acc;
    }
    if (t < FOUT) {
        float acc = blin[t];
        for (int m = 0; m < HID; m++) acc += b2[m] * Wlin[m * FOUT + t];
        g_bf[t] = acc;
    }
}

// agg2 row (128 feats) via CSR gather, reduce straight into pooled sums
__global__ void k_agg2(const int* __restrict__ batch) {
    int warp = (blockIdx.x * blockDim.x + threadIdx.x) >> 5;
    int lane = threadIdx.x & 31;
    if (warp >= NN) return;
    int beg = g_off[warp], end = g_off[warp + 1];
    const float4* h4 = (const float4*)g_h1;
    float4 acc = make_float4(0.f, 0.f, 0.f, 0.f);
    int j = beg;
    // 4-wide unroll for MLP on the random h1 loads
    for (; j + 3 < end; j += 4) {
        int c0 = g_col[j],   c1 = g_col[j+1], c2 = g_col[j+2], c3 = g_col[j+3];
        float w0 = g_w[j],   w1 = g_w[j+1],   w2 = g_w[j+2],   w3 = g_w[j+3];
        float4 v0 = h4[c0 * 32 + lane];
        float4 v1 = h4[c1 * 32 + lane];
        float4 v2 = h4[c2 * 32 + lane];
        float4 v3 = h4[c3 * 32 + lane];
        acc.x += w0*v0.x + w1*v1.x + w2*v2.x + w3*v3.x;
        acc.y += w0*v0.y + w1*v1.y + w2*v2.y + w3*v3.y;
        acc.z += w0*v0.z + w1*v1.z + w2*v2.z + w3*v3.z;
        acc.w += w0*v0.w + w1*v1.w + w2*v2.w + w3*v3.w;
    }
    for (; j < end; j++) {
        int c = g_col[j]; float wt = g_w[j];
        float4 v = h4[c * 32 + lane];
        acc.x += wt * v.x; acc.y += wt * v.y; acc.z += wt * v.z; acc.w += wt * v.w;
    }
    float* p = &g_pool[batch[warp] * HID + lane * 4];
    atomicAdd(p + 0, acc.x);
    atomicAdd(p + 1, acc.y);
    atomicAdd(p + 2, acc.z);
    atomicAdd(p + 3, acc.w);
}

// out[g] = (pool[g]/cnt) @ Wf + bf   (warp per graph, lanes 0..18)
__global__ void k_out(const float* __restrict__ blin, float* __restrict__ out) {
    int warp = (blockIdx.x * blockDim.x + threadIdx.x) >> 5;
    int lane = threadIdx.x & 31;
    if (warp >= NG || lane >= FOUT) return;
    int cnt = g_gcnt[warp];
    float inv = (cnt > 0) ? (1.0f / (float)cnt) : 0.0f;
    float acc = (cnt > 0) ? g_bf[lane] : blin[lane];
    for (int f = 0; f < HID; f++)
        acc += (g_pool[warp * HID + f] * inv) * g_wf[f * FOUT + lane];
    out[warp * FOUT + lane] = acc;
}

extern "C" void kernel_launch(void* const* d_in, const int* in_sizes, int n_in,
                              void* d_out, int out_size) {
    const float* x    = (const float*)d_in[0];
    const int*   esrc = (const int*)d_in[1];
    const int*   edst = (const int*)d_in[2];
    const int*   batch= (const int*)d_in[3];
    const float* W1   = (const float*)d_in[4];
    const float* b1   = (const float*)d_in[5];
    const float* W2   = (const float*)d_in[6];
    const float* b2   = (const float*)d_in[7];
    const float* Wlin = (const float*)d_in[8];
    const float* blin = (const float*)d_in[9];
    float* out = (float*)d_out;

    k_init <<<(NG * HID + 255) / 256, 256>>>();
    k_deg  <<<(NE + 255) / 256, 256>>>(edst);
    k_dinv <<<(NN + 255) / 256, 256>>>(batch);
    k_scanA<<<NB, SCAN_B>>>();
    k_scanB<<<1, 128>>>();
    k_scanC<<<(NN + 255) / 256, 256>>>();
    k_fill <<<(NT + 255) / 256, 256>>>(esrc, edst);
    k_agg1 <<<(NN * 32 + 255) / 256, 256>>>(x);
    k_gemm1<<<(NN + GB_NODES - 1) / GB_NODES, 128>>>(W1, b1);
    k_fuse <<<10, 256>>>(W2, Wlin, b2, blin);
    k_agg2 <<<(NN * 32 + 255) / 256, 256>>>(batch);
    k_out  <<<(NG * 32 + 255) / 256, 256>>>(blin, out);
}

// round 3
// speedup vs baseline: 2.4383x; 1.4371x over previous
#include <cuda_runtime.h>
#include <cuda_bf16.h>
#include <cuda_fp16.h>

#define NN   100000
#define NE   1600000
#define NG   4096
#define HID  128
#define FIN  11
#define FPAD 16
#define FOUT 19
#define NT   (NE + NN)   // edges + self loops
#define SCAN_B 1024
#define NB   ((NN + SCAN_B - 1) / SCAN_B)   // 98
#define NPW  8           // nodes per warp in agg2

// ---- scratch (static device globals; no allocation) ----
__device__ int   g_cnt[NN];
__device__ float g_dinv[NN];
__device__ int   g_off[NN + 1];
__device__ int   g_cur[NN];
__device__ int   g_col[NT];
__device__ int   g_bsum[NB];
__device__ int   g_bpre[NB];
__device__ __align__(16) __half g_xsh[NN * FPAD];   // dinv[i] * x[i], fp16, padded
__device__ float g_agg1[NN * FPAD];                 // dinv[i] * sum xs[col]
__device__ __align__(16) __half g_h1h[NN * HID];    // dinv[i] * relu(h1), fp16
__device__ float g_pool[NG * HID];
__device__ int   g_gcnt[NG];
__device__ float g_wf[HID * FOUT];
__device__ float g_bf[FOUT];

// ---- kernels ----
__global__ void k_init() {
    int i = blockIdx.x * blockDim.x + threadIdx.x;
    if (i < NN)        g_cnt[i] = 1;       // self-loop
    if (i < NG * HID)  g_pool[i] = 0.0f;
    if (i < NG)        g_gcnt[i] = 0;
}

__global__ void k_deg(const int* __restrict__ dst) {
    int e = blockIdx.x * blockDim.x + threadIdx.x;
    if (e < NE) atomicAdd(&g_cnt[dst[e]], 1);
}

// dinv, per-graph node counts, and premultiplied fp16 features xs = dinv[i]*x[i]
__global__ void k_dinv(const int* __restrict__ batch, const float* __restrict__ x) {
    int i = blockIdx.x * blockDim.x + threadIdx.x;
    if (i >= NN) return;
    float di = rsqrtf((float)g_cnt[i]);
    g_dinv[i] = di;
    atomicAdd(&g_gcnt[batch[i]], 1);
    __half* row = &g_xsh[i * FPAD];
#pragma unroll
    for (int k = 0; k < FIN; k++) row[k] = __float2half(di * x[i * FIN + k]);
#pragma unroll
    for (int k = FIN; k < FPAD; k++) row[k] = __float2half(0.0f);
}

// ---- 3-phase parallel scan of g_cnt -> g_off (exclusive), g_cur ----
__global__ void k_scanA() {
    __shared__ int s[SCAN_B];
    int t = threadIdx.x;
    int i = blockIdx.x * SCAN_B + t;
    int c = (i < NN) ? g_cnt[i] : 0;
    s[t] = c;
    __syncthreads();
#pragma unroll
    for (int off = 1; off < SCAN_B; off <<= 1) {
        int v = (t >= off) ? s[t - off] : 0;
        __syncthreads();
        if (t >= off) s[t] += v;
        __syncthreads();
    }
    if (i < NN) g_off[i] = s[t] - c;
    if (t == SCAN_B - 1) g_bsum[blockIdx.x] = s[t];
}

__global__ void k_scanB() {
    __shared__ int s[128];
    int t = threadIdx.x;
    int v = (t < NB) ? g_bsum[t] : 0;
    s[t] = v;
    __syncthreads();
#pragma unroll
    for (int off = 1; off < 128; off <<= 1) {
        int u = (t >= off) ? s[t - off] : 0;
        __syncthreads();
        if (t >= off) s[t] += u;
        __syncthreads();
    }
    if (t < NB) g_bpre[t] = s[t] - v;
    if (t == 127) g_off[NN] = s[127];
}

__global__ void k_scanC() {
    int i = blockIdx.x * blockDim.x + threadIdx.x;
    if (i < NN) {
        int o = g_off[i] + g_bpre[i / SCAN_B];
        g_off[i] = o;
        g_cur[i] = o;
    }
}

__global__ void k_fill(const int* __restrict__ src, const int* __restrict__ dst) {
    int t = blockIdx.x * blockDim.x + threadIdx.x;
    if (t >= NT) return;
    int s, d;
    if (t < NE) { s = src[t]; d = dst[t]; }
    else        { s = d = t - NE; }
    int p = atomicAdd(&g_cur[d], 1);
    g_col[p] = s;
}

// agg1[i] = dinv[i] * sum_j xs[col[j]]  (warp/node, lanes 0..7 each hold half2 pair)
__global__ void k_agg1() {
    int warp = (blockIdx.x * blockDim.x + threadIdx.x) >> 5;
    int lane = threadIdx.x & 31;
    if (warp >= NN) return;
    int beg = g_off[warp], end = g_off[warp + 1];
    const __half2* xs2 = (const __half2*)g_xsh;   // 8 half2 per row
    float2 acc = make_float2(0.f, 0.f);
    if (lane < 8) {
        int j = beg;
        for (; j + 3 < end; j += 4) {
            int c0 = g_col[j], c1 = g_col[j+1], c2 = g_col[j+2], c3 = g_col[j+3];
            float2 a0 = __half22float2(xs2[c0 * 8 + lane]);
            float2 a1 = __half22float2(xs2[c1 * 8 + lane]);
            float2 a2 = __half22float2(xs2[c2 * 8 + lane]);
            float2 a3 = __half22float2(xs2[c3 * 8 + lane]);
            acc.x += a0.x + a1.x + a2.x + a3.x;
            acc.y += a0.y + a1.y + a2.y + a3.y;
        }
        for (; j < end; j++) {
            float2 a = __half22float2(xs2[g_col[j] * 8 + lane]);
            acc.x += a.x; acc.y += a.y;
        }
        float di = g_dinv[warp];
        float2* out = (float2*)&g_agg1[warp * FPAD];
        out[lane] = make_float2(di * acc.x, di * acc.y);
    }
}

// h1 = dinv * relu(agg1 @ W1 + b1) stored fp16; 128 threads, 16 nodes per block
#define GB_NODES 16
__global__ void k_gemm1(const float* __restrict__ W1, const float* __restrict__ b1) {
    __shared__ float sW[FIN * HID];
    __shared__ float sb[HID];
    __shared__ float srow[GB_NODES * FIN];
    __shared__ float sdi[GB_NODES];
    int t = threadIdx.x;
    for (int k = t; k < FIN * HID; k += 128) sW[k] = W1[k];
    sb[t] = b1[t];
    int nb = blockIdx.x * GB_NODES;
    for (int k = t; k < GB_NODES * FIN; k += 128) {
        int node = nb + k / FIN;
        srow[k] = (node < NN) ? g_agg1[node * FPAD + (k % FIN)] : 0.0f;
    }
    if (t < GB_NODES) {
        int node = nb + t;
        sdi[t] = (node < NN) ? g_dinv[node] : 0.0f;
    }
    __syncthreads();
    float wc[FIN];
#pragma unroll
    for (int k = 0; k < FIN; k++) wc[k] = sW[k * HID + t];
#pragma unroll
    for (int n = 0; n < GB_NODES; n++) {
        int node = nb + n;
        if (node >= NN) break;
        float acc = sb[t];
#pragma unroll
        for (int k = 0; k < FIN; k++) acc += srow[n * FIN + k] * wc[k];
        g_h1h[(size_t)node * HID + t] = __float2half(sdi[n] * fmaxf(acc, 0.0f));
    }
}

// fuse W2@Wlin and b2@Wlin+blin
__global__ void k_fuse(const float* __restrict__ W2, const float* __restrict__ Wlin,
                       const float* __restrict__ b2, const float* __restrict__ blin) {
    int t = blockIdx.x * blockDim.x + threadIdx.x;
    if (t < HID * FOUT) {
        int f = t / FOUT, o = t % FOUT;
        float acc = 0.0f;
        for (int m = 0; m < HID; m++) acc += W2[f * HID + m] * Wlin[m * FOUT + o];
        g_wf[t] = acc;
    }
    if (t < FOUT) {
        float acc = blin[t];
        for (int m = 0; m < HID; m++) acc += b2[m] * Wlin[m * FOUT + t];
        g_bf[t] = acc;
    }
}

// agg2: warp handles NPW consecutive nodes; fp16 gather; batched pool atomics
__global__ void k_agg2(const int* __restrict__ batch) {
    int warp = (blockIdx.x * blockDim.x + threadIdx.x) >> 5;
    int lane = threadIdx.x & 31;
    int n0 = warp * NPW;
    if (n0 >= NN) return;
    int nend = n0 + NPW; if (nend > NN) nend = NN;
    const uint2* h2 = (const uint2*)g_h1h;   // 32 x 8B slots per 128-feat row
    float4 acc = make_float4(0.f, 0.f, 0.f, 0.f);
    int cur_b = batch[n0];
    for (int node = n0; node < nend; node++) {
        int b = batch[node];
        if (b != cur_b) {
            float* p = &g_pool[cur_b * HID + lane * 4];
            atomicAdd(p + 0, acc.x); atomicAdd(p + 1, acc.y);
            atomicAdd(p + 2, acc.z); atomicAdd(p + 3, acc.w);
            acc = make_float4(0.f, 0.f, 0.f, 0.f);
            cur_b = b;
        }
        int beg = g_off[node], end = g_off[node + 1];
        float4 r = make_float4(0.f, 0.f, 0.f, 0.f);
        int j = beg;
        for (; j + 3 < end; j += 4) {
            int c0 = g_col[j], c1 = g_col[j+1], c2 = g_col[j+2], c3 = g_col[j+3];
            uint2 v0 = h2[c0 * 32 + lane];
            uint2 v1 = h2[c1 * 32 + lane];
            uint2 v2 = h2[c2 * 32 + lane];
            uint2 v3 = h2[c3 * 32 + lane];
            float2 a, bb;
            a = __half22float2(*(__half2*)&v0.x); bb = __half22float2(*(__half2*)&v0.y);
            r.x += a.x; r.y += a.y; r.z += bb.x; r.w += bb.y;
            a = __half22float2(*(__half2*)&v1.x); bb = __half22float2(*(__half2*)&v1.y);
            r.x += a.x; r.y += a.y; r.z += bb.x; r.w += bb.y;
            a = __half22float2(*(__half2*)&v2.x); bb = __half22float2(*(__half2*)&v2.y);
            r.x += a.x; r.y += a.y; r.z += bb.x; r.w += bb.y;
            a = __half22float2(*(__half2*)&v3.x); bb = __half22float2(*(__half2*)&v3.y);
            r.x += a.x; r.y += a.y; r.z += bb.x; r.w += bb.y;
        }
        for (; j < end; j++) {
            uint2 v = h2[g_col[j] * 32 + lane];
            float2 a = __half22float2(*(__half2*)&v.x);
            float2 bb = __half22float2(*(__half2*)&v.y);
            r.x += a.x; r.y += a.y; r.z += bb.x; r.w += bb.y;
        }
        float di = g_dinv[node];
        acc.x += di * r.x; acc.y += di * r.y;
        acc.z += di * r.z; acc.w += di * r.w;
    }
    float* p = &g_pool[cur_b * HID + lane * 4];
    atomicAdd(p + 0, acc.x); atomicAdd(p + 1, acc.y);
    atomicAdd(p + 2, acc.z); atomicAdd(p + 3, acc.w);
}

// out[g] = (pool[g]/cnt) @ Wf + bf
__global__ void k_out(const float* __restrict__ blin, float* __restrict__ out) {
    int warp = (blockIdx.x * blockDim.x + threadIdx.x) >> 5;
    int lane = threadIdx.x & 31;
    if (warp >= NG || lane >= FOUT) return;
    int cnt = g_gcnt[warp];
    float inv = (cnt > 0) ? (1.0f / (float)cnt) : 0.0f;
    float acc = (cnt > 0) ? g_bf[lane] : blin[lane];
    for (int f = 0; f < HID; f++)
        acc += (g_pool[warp * HID + f] * inv) * g_wf[f * FOUT + lane];
    out[warp * FOUT + lane] = acc;
}

extern "C" void kernel_launch(void* const* d_in, const int* in_sizes, int n_in,
                              void* d_out, int out_size) {
    const float* x    = (const float*)d_in[0];
    const int*   esrc = (const int*)d_in[1];
    const int*   edst = (const int*)d_in[2];
    const int*   batch= (const int*)d_in[3];
    const float* W1   = (const float*)d_in[4];
    const float* b1   = (const float*)d_in[5];
    const float* W2   = (const float*)d_in[6];
    const float* b2   = (const float*)d_in[7];
    const float* Wlin = (const float*)d_in[8];
    const float* blin = (const float*)d_in[9];
    float* out = (float*)d_out;

    k_init <<<(NG * HID + 255) / 256, 256>>>();
    k_deg  <<<(NE + 255) / 256, 256>>>(edst);
    k_dinv <<<(NN + 255) / 256, 256>>>(batch, x);
    k_scanA<<<NB, SCAN_B>>>();
    k_scanB<<<1, 128>>>();
    k_scanC<<<(NN + 255) / 256, 256>>>();
    k_fill <<<(NT + 255) / 256, 256>>>(esrc, edst);
    k_agg1 <<<(NN * 32 + 255) / 256, 256>>>();
    k_gemm1<<<(NN + GB_NODES - 1) / GB_NODES, 128>>>(W1, b1);
    k_fuse <<<10, 256>>>(W2, Wlin, b2, blin);
    {
        int warps = (NN + NPW - 1) / NPW;
        k_agg2 <<<(warps * 32 + 255) / 256, 256>>>(batch);
    }
    k_out  <<<(NG * 32 + 255) / 256, 256>>>(blin, out);
}

// round 4
// speedup vs baseline: 2.5104x; 1.0296x over previous
#include <cuda_runtime.h>
#include <cuda_bf16.h>
#include <cuda_fp16.h>

#define NN   100000
#define NE   1600000
#define NG   4096
#define HID  128
#define FIN  11
#define FPAD 16
#define FOUT 19
#define NT   (NE + NN)   // edges + self loops
#define SCAN_B 1024
#define NB   ((NN + SCAN_B - 1) / SCAN_B)   // 98
#define NPW  8           // nodes per warp in agg2

// ---- scratch (static device globals; no allocation) ----
__device__ int   g_cnt[NN];
__device__ float g_dinv[NN];
__device__ int   g_off[NN + 1];
__device__ int   g_cur[NN];
__device__ int   g_col[NT];
__device__ int   g_bsum[NB];
__device__ int   g_bpre[NB];
__device__ __align__(16) __half g_xsh[NN * FPAD];   // dinv[i] * x[i], fp16, padded
__device__ float g_agg1[NN * FPAD];                 // dinv[i] * sum xs[col]
__device__ __align__(16) __half g_h1h[NN * HID];    // dinv[i] * relu(h1), fp16
__device__ float g_pool[NG * HID];
__device__ int   g_gcnt[NG];
__device__ float g_wf[HID * FOUT];
__device__ float g_bf[FOUT];

// ---- kernels ----
__global__ void k_init() {
    int i = blockIdx.x * blockDim.x + threadIdx.x;
    if (i < NN)        g_cnt[i] = 1;       // self-loop
    if (i < NG * HID)  g_pool[i] = 0.0f;
    if (i < NG)        g_gcnt[i] = 0;
}

__global__ void k_deg(const int* __restrict__ dst) {
    int e = blockIdx.x * blockDim.x + threadIdx.x;
    if (e < NE) atomicAdd(&g_cnt[dst[e]], 1);
}

// ---- scan phase A fused with dinv / xs premult / graph counts ----
__global__ void k_scanA(const int* __restrict__ batch, const float* __restrict__ x) {
    __shared__ int s[SCAN_B];
    int t = threadIdx.x;
    int i = blockIdx.x * SCAN_B + t;
    int c = (i < NN) ? g_cnt[i] : 0;
    s[t] = c;
    // fused per-node work (independent of the scan)
    if (i < NN) {
        float di = rsqrtf((float)c);
        g_dinv[i] = di;
        atomicAdd(&g_gcnt[batch[i]], 1);
        __half* row = &g_xsh[i * FPAD];
#pragma unroll
        for (int k = 0; k < FIN; k++) row[k] = __float2half(di * x[i * FIN + k]);
#pragma unroll
        for (int k = FIN; k < FPAD; k++) row[k] = __float2half(0.0f);
    }
    __syncthreads();
#pragma unroll
    for (int off = 1; off < SCAN_B; off <<= 1) {
        int v = (t >= off) ? s[t - off] : 0;
        __syncthreads();
        if (t >= off) s[t] += v;
        __syncthreads();
    }
    if (i < NN) g_off[i] = s[t] - c;
    if (t == SCAN_B - 1) g_bsum[blockIdx.x] = s[t];
}

__global__ void k_scanB() {
    __shared__ int s[128];
    int t = threadIdx.x;
    int v = (t < NB) ? g_bsum[t] : 0;
    s[t] = v;
    __syncthreads();
#pragma unroll
    for (int off = 1; off < 128; off <<= 1) {
        int u = (t >= off) ? s[t - off] : 0;
        __syncthreads();
        if (t >= off) s[t] += u;
        __syncthreads();
    }
    if (t < NB) g_bpre[t] = s[t] - v;
    if (t == 127) g_off[NN] = s[127];
}

__global__ void k_scanC() {
    int i = blockIdx.x * blockDim.x + threadIdx.x;
    if (i < NN) {
        int o = g_off[i] + g_bpre[i / SCAN_B];
        g_off[i] = o;
        g_cur[i] = o;
    }
}

__global__ void k_fill(const int* __restrict__ src, const int* __restrict__ dst) {
    int t = blockIdx.x * blockDim.x + threadIdx.x;
    if (t >= NT) return;
    int s, d;
    if (t < NE) { s = src[t]; d = dst[t]; }
    else        { s = d = t - NE; }
    int p = atomicAdd(&g_cur[d], 1);
    g_col[p] = s;
}

// agg1[i] = dinv[i] * sum_j xs[col[j]]
// warp/node; lane = 8*e + f : edge-group e (0..3), feature pair f (0..7)
__global__ void k_agg1() {
    int warp = (blockIdx.x * blockDim.x + threadIdx.x) >> 5;
    int lane = threadIdx.x & 31;
    if (warp >= NN) return;
    int beg = g_off[warp], end = g_off[warp + 1];
    int e = lane >> 3, f = lane & 7;
    const __half2* xs2 = (const __half2*)g_xsh;   // 8 half2 per row
    float2 acc = make_float2(0.f, 0.f);
    for (int j = beg + e; j < end; j += 4) {
        float2 a = __half22float2(xs2[g_col[j] * 8 + f]);
        acc.x += a.x; acc.y += a.y;
    }
    acc.x += __shfl_xor_sync(0xffffffff, acc.x, 8);
    acc.y += __shfl_xor_sync(0xffffffff, acc.y, 8);
    acc.x += __shfl_xor_sync(0xffffffff, acc.x, 16);
    acc.y += __shfl_xor_sync(0xffffffff, acc.y, 16);
    if (lane < 8) {
        float di = g_dinv[warp];
        ((float2*)&g_agg1[warp * FPAD])[f] = make_float2(di * acc.x, di * acc.y);
    }
}

// h1 = dinv * relu(agg1 @ W1 + b1) stored fp16; 128 threads, 64 nodes per block
#define GB_NODES 64
__global__ void k_gemm1(const float* __restrict__ W1, const float* __restrict__ b1) {
    __shared__ float sW[FIN * HID];
    __shared__ float sb[HID];
    __shared__ float srow[GB_NODES * FIN];
    __shared__ float sdi[GB_NODES];
    int t = threadIdx.x;
    for (int k = t; k < FIN * HID; k += 128) sW[k] = W1[k];
    sb[t] = b1[t];
    int nb = blockIdx.x * GB_NODES;
    for (int k = t; k < GB_NODES * FIN; k += 128) {
        int node = nb + k / FIN;
        srow[k] = (node < NN) ? g_agg1[node * FPAD + (k % FIN)] : 0.0f;
    }
    for (int k = t; k < GB_NODES; k += 128) {
        int node = nb + k;
        sdi[k] = (node < NN) ? g_dinv[node] : 0.0f;
    }
    __syncthreads();
    float wc[FIN];
#pragma unroll
    for (int k = 0; k < FIN; k++) wc[k] = sW[k * HID + t];
    for (int n = 0; n < GB_NODES; n++) {
        int node = nb + n;
        if (node >= NN) break;
        float acc = sb[t];
#pragma unroll
        for (int k = 0; k < FIN; k++) acc += srow[n * FIN + k] * wc[k];
        g_h1h[(size_t)node * HID + t] = __float2half(sdi[n] * fmaxf(acc, 0.0f));
    }
}

// fuse W2@Wlin and b2@Wlin+blin
__global__ void k_fuse(const float* __restrict__ W2, const float* __restrict__ Wlin,
                       const float* __restrict__ b2, const float* __restrict__ blin) {
    int t = blockIdx.x * blockDim.x + threadIdx.x;
    if (t < HID * FOUT) {
        int f = t / FOUT, o = t % FOUT;
        float acc = 0.0f;
        for (int m = 0; m < HID; m++) acc += W2[f * HID + m] * Wlin[m * FOUT + o];
        g_wf[t] = acc;
    }
    if (t < FOUT) {
        float acc = blin[t];
        for (int m = 0; m < HID; m++) acc += b2[m] * Wlin[m * FOUT + t];
        g_bf[t] = acc;
    }
}

// agg2: warp handles NPW consecutive nodes; fp16 gather; batched pool atomics
__global__ void k_agg2(const int* __restrict__ batch) {
    int warp = (blockIdx.x * blockDim.x + threadIdx.x) >> 5;
    int lane = threadIdx.x & 31;
    int n0 = warp * NPW;
    if (n0 >= NN) return;
    int nend = n0 + NPW; if (nend > NN) nend = NN;
    const uint2* h2 = (const uint2*)g_h1h;   // 32 x 8B slots per 128-feat row
    float4 acc = make_float4(0.f, 0.f, 0.f, 0.f);
    int cur_b = batch[n0];
    for (int node = n0; node < nend; node++) {
        int b = batch[node];
        if (b != cur_b) {
            float* p = &g_pool[cur_b * HID + lane * 4];
            atomicAdd(p + 0, acc.x); atomicAdd(p + 1, acc.y);
            atomicAdd(p + 2, acc.z); atomicAdd(p + 3, acc.w);
            acc = make_float4(0.f, 0.f, 0.f, 0.f);
            cur_b = b;
        }
        int beg = g_off[node], end = g_off[node + 1];
        float4 r = make_float4(0.f, 0.f, 0.f, 0.f);
        int j = beg;
        for (; j + 3 < end; j += 4) {
            int c0 = g_col[j], c1 = g_col[j+1], c2 = g_col[j+2], c3 = g_col[j+3];
            uint2 v0 = h2[c0 * 32 + lane];
            uint2 v1 = h2[c1 * 32 + lane];
            uint2 v2 = h2[c2 * 32 + lane];
            uint2 v3 = h2[c3 * 32 + lane];
            float2 a, bb;
            a = __half22float2(*(__half2*)&v0.x); bb = __half22float2(*(__half2*)&v0.y);
            r.x += a.x; r.y += a.y; r.z += bb.x; r.w += bb.y;
            a = __half22float2(*(__half2*)&v1.x); bb = __half22float2(*(__half2*)&v1.y);
            r.x += a.x; r.y += a.y; r.z += bb.x; r.w += bb.y;
            a = __half22float2(*(__half2*)&v2.x); bb = __half22float2(*(__half2*)&v2.y);
            r.x += a.x; r.y += a.y; r.z += bb.x; r.w += bb.y;
            a = __half22float2(*(__half2*)&v3.x); bb = __half22float2(*(__half2*)&v3.y);
            r.x += a.x; r.y += a.y; r.z += bb.x; r.w += bb.y;
        }
        for (; j < end; j++) {
            uint2 v = h2[g_col[j] * 32 + lane];
            float2 a = __half22float2(*(__half2*)&v.x);
            float2 bb = __half22float2(*(__half2*)&v.y);
            r.x += a.x; r.y += a.y; r.z += bb.x; r.w += bb.y;
        }
        float di = g_dinv[node];
        acc.x += di * r.x; acc.y += di * r.y;
        acc.z += di * r.z; acc.w += di * r.w;
    }
    float* p = &g_pool[cur_b * HID + lane * 4];
    atomicAdd(p + 0, acc.x); atomicAdd(p + 1, acc.y);
    atomicAdd(p + 2, acc.z); atomicAdd(p + 3, acc.w);
}

// out[g] = (pool[g]/cnt) @ Wf + bf
__global__ void k_out(const float* __restrict__ blin, float* __restrict__ out) {
    int warp = (blockIdx.x * blockDim.x + threadIdx.x) >> 5;
    int lane = threadIdx.x & 31;
    if (warp >= NG || lane >= FOUT) return;
    int cnt = g_gcnt[warp];
    float inv = (cnt > 0) ? (1.0f / (float)cnt) : 0.0f;
    float acc = (cnt > 0) ? g_bf[lane] : blin[lane];
    for (int f = 0; f < HID; f++)
        acc += (g_pool[warp * HID + f] * inv) * g_wf[f * FOUT + lane];
    out[warp * FOUT + lane] = acc;
}

extern "C" void kernel_launch(void* const* d_in, const int* in_sizes, int n_in,
                              void* d_out, int out_size) {
    const float* x    = (const float*)d_in[0];
    const int*   esrc = (const int*)d_in[1];
    const int*   edst = (const int*)d_in[2];
    const int*   batch= (const int*)d_in[3];
    const float* W1   = (const float*)d_in[4];
    const float* b1   = (const float*)d_in[5];
    const float* W2   = (const float*)d_in[6];
    const float* b2   = (const float*)d_in[7];
    const float* Wlin = (const float*)d_in[8];
    const float* blin = (const float*)d_in[9];
    float* out = (float*)d_out;

    k_init <<<(NG * HID + 255) / 256, 256>>>();
    k_deg  <<<(NE + 255) / 256, 256>>>(edst);
    k_scanA<<<NB, SCAN_B>>>(batch, x);
    k_scanB<<<1, 128>>>();
    k_scanC<<<(NN + 255) / 256, 256>>>();
    k_fill <<<(NT + 255) / 256, 256>>>(esrc, edst);
    k_agg1 <<<(NN * 32 + 255) / 256, 256>>>();
    k_gemm1<<<(NN + GB_NODES - 1) / GB_NODES, 128>>>(W1, b1);
    k_fuse <<<10, 256>>>(W2, Wlin, b2, blin);
    {
        int warps = (NN + NPW - 1) / NPW;
        k_agg2 <<<(warps * 32 + 255) / 256, 256>>>(batch);
    }
    k_out  <<<(NG * 32 + 255) / 256, 256>>>(blin, out);
}